// round 3
// baseline (speedup 1.0000x reference)
#include <cuda_runtime.h>

// Problem constants
#define BATCH    4096
#define T_LEN    1024
#define D_IN     3
#define H_DIM    64
#define G_DIM    192     // 3*H
#define TB       64      // batch rows per CTA
#define NTHREADS 256
#define XC       16      // x timesteps staged per chunk

// Dynamic SMEM partition (floats):
//   WhhS [64][192]  (k-major transposed W_hh)   12288
//   HsS  [64][64]   (h state, k-major: [k][i])   4096
//   xsS  [48][64]   (x chunk, [t*3+d][i])        3072
#define SMEM_FLOATS (12288 + 4096 + 48*64)
#define SMEM_BYTES  (SMEM_FLOATS * 4)

// Scratch for final hidden states (allocation-free rule: __device__ global)
__device__ float g_hfinal[2u * BATCH * H_DIM];

typedef unsigned long long u64;

__device__ __forceinline__ u64 pack2(float lo, float hi) {
    u64 r; asm("mov.b64 %0, {%1,%2};" : "=l"(r) : "f"(lo), "f"(hi)); return r;
}
__device__ __forceinline__ void unpack2(u64 v, float& lo, float& hi) {
    asm("mov.b64 {%0,%1}, %2;" : "=f"(lo), "=f"(hi) : "l"(v));
}
// Packed dual fp32 FMA (FFMA2) — sm_100+ PTX only path
__device__ __forceinline__ void ffma2(u64& d, u64 a, u64 b) {
    asm("fma.rn.f32x2 %0, %1, %2, %0;" : "+l"(d) : "l"(a), "l"(b));
}

__device__ __forceinline__ float sigm(float a) {
    a = fminf(30.f, fmaxf(-30.f, a));
    float e = __expf(-a);
    return __fdividef(1.f, 1.f + e);
}
__device__ __forceinline__ float tanh_f(float a) {
    a = fminf(15.f, fmaxf(-15.f, a));
    float e = __expf(-2.f * a);
    return __fdividef(1.f - e, 1.f + e);
}

// ---------------------------------------------------------------------------
// GRU kernel: grid = 128 CTAs. CTA handles one sequence (blockIdx>>6) and a
// 64-row batch tile. Per step: Hg[64,192] = H[64,64] @ Whh^T via register-tiled
// SMEM GEMM in packed f32x2, then fused elementwise gate update.
// Thread tile: 4 batch rows (i0..i0+3) x 4 hidden units (h0..h0+3), computing
// all 3 gates for that tile -> no cross-thread gate exchange needed.
// ---------------------------------------------------------------------------
__global__ __launch_bounds__(NTHREADS, 1)
void gru_kernel(const float* __restrict__ x1, const float* __restrict__ x2,
                const float* __restrict__ Wih, const float* __restrict__ Whh,
                const float* __restrict__ bih_g, const float* __restrict__ bhh_g)
{
    extern __shared__ float sm[];
    float* WhhS = sm;                 // [64][192]
    float* HsS  = sm + 12288;         // [64][64]  (HsS[k*64+i] = h[i][k])
    float* xsS  = sm + 12288 + 4096;  // [48][64]  (xsS[(t*3+d)*64+i])

    const int tid = threadIdx.x;
    const int seq = blockIdx.x >> 6;
    const int b0  = (blockIdx.x & 63) * TB;
    const float* xg = (seq == 0) ? x1 : x2;

    const int i0 = (tid & 15) * 4;   // batch-row tile
    const int h0 = (tid >> 4) * 4;   // hidden-unit tile

    // Stage W_hh transposed: WhhS[k][j] = W_hh[j][k]
    for (int idx = tid; idx < H_DIM * G_DIM; idx += NTHREADS) {
        int k = idx / G_DIM, j = idx - k * G_DIM;
        WhhS[idx] = Whh[j * H_DIM + k];
    }
    // h0 state = 0
    for (int idx = tid; idx < H_DIM * TB; idx += NTHREADS) HsS[idx] = 0.f;

    // Per-thread weights/biases in registers
    float wih[3][4][3];
    float bihr[3][4];
    u64   bhh2[3][2];
    #pragma unroll
    for (int g = 0; g < 3; ++g) {
        #pragma unroll
        for (int h = 0; h < 4; ++h) {
            int row = g * 64 + h0 + h;
            bihr[g][h] = bih_g[row];
            #pragma unroll
            for (int d = 0; d < 3; ++d) wih[g][h][d] = Wih[row * 3 + d];
        }
        bhh2[g][0] = pack2(bhh_g[g * 64 + h0 + 0], bhh_g[g * 64 + h0 + 1]);
        bhh2[g][1] = pack2(bhh_g[g * 64 + h0 + 2], bhh_g[g * 64 + h0 + 3]);
    }

    float hprev[4][4];   // [h][i], this thread's tile of the state
    #pragma unroll
    for (int h = 0; h < 4; ++h)
        #pragma unroll
        for (int i = 0; i < 4; ++i) hprev[h][i] = 0.f;

    __syncthreads();

    for (int t0 = 0; t0 < T_LEN; t0 += XC) {
        // Stage x[t0..t0+15] transposed into SMEM (coalesced 16B global loads)
        for (int idx = tid; idx < TB * 12; idx += NTHREADS) {
            int row = idx / 12, q = idx - row * 12;
            const float4 v = *(const float4*)(xg + (size_t)(b0 + row) * (T_LEN * D_IN)
                                                 + t0 * D_IN + q * 4);
            xsS[(q * 4 + 0) * 64 + row] = v.x;
            xsS[(q * 4 + 1) * 64 + row] = v.y;
            xsS[(q * 4 + 2) * 64 + row] = v.z;
            xsS[(q * 4 + 3) * 64 + row] = v.w;
        }
        __syncthreads();

        #pragma unroll 1
        for (int tt = 0; tt < XC; ++tt) {
            // ---- GEMM: acc[g][q][i] packs gates (h0+2q, h0+2q+1) for row i0+i
            u64 acc[3][2][4];
            #pragma unroll
            for (int g = 0; g < 3; ++g)
                #pragma unroll
                for (int q = 0; q < 2; ++q)
                    #pragma unroll
                    for (int i = 0; i < 4; ++i) acc[g][q][i] = bhh2[g][q];

            #pragma unroll 8
            for (int k = 0; k < H_DIM; ++k) {
                const float4 av = *(const float4*)(HsS + k * 64 + i0);   // conflict-free
                u64 ad[4] = { pack2(av.x, av.x), pack2(av.y, av.y),
                              pack2(av.z, av.z), pack2(av.w, av.w) };
                #pragma unroll
                for (int g = 0; g < 3; ++g) {
                    const ulonglong2 wv =
                        *(const ulonglong2*)(WhhS + k * G_DIM + g * 64 + h0); // broadcast
                    #pragma unroll
                    for (int i = 0; i < 4; ++i) {
                        ffma2(acc[g][0][i], ad[i], wv.x);
                        ffma2(acc[g][1][i], ad[i], wv.y);
                    }
                }
            }
            __syncthreads();   // all Hs reads done before rewriting Hs

            // ---- x contribution for my 4 rows
            float xr4[3][4];
            #pragma unroll
            for (int d = 0; d < 3; ++d) {
                const float4 v = *(const float4*)(xsS + (tt * 3 + d) * 64 + i0);
                xr4[d][0] = v.x; xr4[d][1] = v.y; xr4[d][2] = v.z; xr4[d][3] = v.w;
            }

            // ---- Fused gate elementwise
            #pragma unroll
            for (int q = 0; q < 2; ++q) {
                float hr[2][4], hz[2][4], hn[2][4];
                #pragma unroll
                for (int i = 0; i < 4; ++i) {
                    unpack2(acc[0][q][i], hr[0][i], hr[1][i]);
                    unpack2(acc[1][q][i], hz[0][i], hz[1][i]);
                    unpack2(acc[2][q][i], hn[0][i], hn[1][i]);
                }
                #pragma unroll
                for (int s = 0; s < 2; ++s) {
                    const int h = 2 * q + s;
                    #pragma unroll
                    for (int i = 0; i < 4; ++i) {
                        float xr = bihr[0][h] + xr4[0][i]*wih[0][h][0]
                                             + xr4[1][i]*wih[0][h][1]
                                             + xr4[2][i]*wih[0][h][2];
                        float xz = bihr[1][h] + xr4[0][i]*wih[1][h][0]
                                             + xr4[1][i]*wih[1][h][1]
                                             + xr4[2][i]*wih[1][h][2];
                        float xn = bihr[2][h] + xr4[0][i]*wih[2][h][0]
                                             + xr4[1][i]*wih[2][h][1]
                                             + xr4[2][i]*wih[2][h][2];
                        float r = sigm(xr + hr[s][i]);
                        float z = sigm(xz + hz[s][i]);
                        float n = tanh_f(xn + r * hn[s][i]);
                        hprev[h][i] = n + z * (hprev[h][i] - n);
                    }
                }
            }

            // ---- Write new state (conflict-free STS.128)
            #pragma unroll
            for (int h = 0; h < 4; ++h)
                *(float4*)(HsS + (h0 + h) * 64 + i0) =
                    make_float4(hprev[h][0], hprev[h][1], hprev[h][2], hprev[h][3]);
            __syncthreads();
        }
    }

    // Final hidden state -> global scratch
    #pragma unroll
    for (int i = 0; i < 4; ++i) {
        float4 v = make_float4(hprev[0][i], hprev[1][i], hprev[2][i], hprev[3][i]);
        *(float4*)(g_hfinal + ((size_t)seq * BATCH + b0 + i0 + i) * H_DIM + h0) = v;
    }
}

// ---------------------------------------------------------------------------
// MLP head: |h1-h2| -> Linear(64,32)+ReLU -> Linear(32,1)+Sigmoid
// One warp per batch row; hidden unit j = lane (32 hidden units = warp width).
// ---------------------------------------------------------------------------
__global__ __launch_bounds__(128)
void mlp_kernel(const float* __restrict__ W1, const float* __restrict__ b1,
                const float* __restrict__ W2, const float* __restrict__ b2,
                float* __restrict__ out)
{
    __shared__ float sW1[32][65];   // padded: conflict-free sW1[lane][k]
    __shared__ float sb1[32], sW2[32];
    const int tid = threadIdx.x;
    for (int idx = tid; idx < 32 * 64; idx += 128) sW1[idx >> 6][idx & 63] = W1[idx];
    if (tid < 32) { sb1[tid] = b1[tid]; sW2[tid] = W2[tid]; }
    __syncthreads();

    const int lane = tid & 31;
    const int row  = blockIdx.x * 4 + (tid >> 5);
    const float* h1 = g_hfinal + (size_t)row * H_DIM;
    const float* h2 = g_hfinal + (size_t)(BATCH + row) * H_DIM;
    float d0 = fabsf(h1[lane]      - h2[lane]);
    float d1 = fabsf(h1[lane + 32] - h2[lane + 32]);

    float acc = sb1[lane];
    #pragma unroll
    for (int k = 0; k < 32; ++k) {
        float v0 = __shfl_sync(0xffffffffu, d0, k);
        float v1 = __shfl_sync(0xffffffffu, d1, k);
        acc += v0 * sW1[lane][k] + v1 * sW1[lane][k + 32];
    }
    float hid = fmaxf(acc, 0.f);
    float p = hid * sW2[lane];
    #pragma unroll
    for (int o = 16; o; o >>= 1) p += __shfl_xor_sync(0xffffffffu, p, o);
    if (lane == 0) out[row] = sigm(p + b2[0]);
}

// ---------------------------------------------------------------------------
extern "C" void kernel_launch(void* const* d_in, const int* in_sizes, int n_in,
                              void* d_out, int out_size)
{
    const float* x1  = (const float*)d_in[0];
    const float* x2  = (const float*)d_in[1];
    const float* Wih = (const float*)d_in[2];
    const float* Whh = (const float*)d_in[3];
    const float* bih = (const float*)d_in[4];
    const float* bhh = (const float*)d_in[5];
    const float* W1  = (const float*)d_in[6];
    const float* b1  = (const float*)d_in[7];
    const float* W2  = (const float*)d_in[8];
    const float* b2  = (const float*)d_in[9];

    cudaFuncSetAttribute((const void*)gru_kernel,
                         cudaFuncAttributeMaxDynamicSharedMemorySize, SMEM_BYTES);

    gru_kernel<<<128, NTHREADS, SMEM_BYTES>>>(x1, x2, Wih, Whh, bih, bhh);
    mlp_kernel<<<BATCH / 4, 128>>>(W1, b1, W2, b2, (float*)d_out);
}

// round 4
// speedup vs baseline: 1.0017x; 1.0017x over previous
#include <cuda_runtime.h>

// Problem constants
#define BATCH    4096
#define T_LEN    1024
#define D_IN     3
#define H_DIM    64
#define G_DIM    192     // 3*H
#define TB       64      // batch rows per CTA
#define NTHREADS 256
#define XC       16      // x timesteps staged per chunk

// Dynamic SMEM partition (floats):
//   WhhS [64][192]  (k-major transposed W_hh)   12288
//   HsS  [64][64]   (h state, k-major: [k][i])   4096
//   xsS  [48][64]   (x chunk, [t*3+d][i])        3072
#define SMEM_FLOATS (12288 + 4096 + 48*64)
#define SMEM_BYTES  (SMEM_FLOATS * 4)

// Scratch for final hidden states (allocation-free rule: __device__ global)
__device__ float g_hfinal[2u * BATCH * H_DIM];

typedef unsigned long long u64;

__device__ __forceinline__ u64 pack2(float lo, float hi) {
    u64 r; asm("mov.b64 %0, {%1,%2};" : "=l"(r) : "f"(lo), "f"(hi)); return r;
}
__device__ __forceinline__ void unpack2(u64 v, float& lo, float& hi) {
    asm("mov.b64 {%0,%1}, %2;" : "=f"(lo), "=f"(hi) : "l"(v));
}
// Packed dual fp32 FMA (FFMA2) — sm_100+ PTX only path
__device__ __forceinline__ void ffma2(u64& d, u64 a, u64 b) {
    asm("fma.rn.f32x2 %0, %1, %2, %0;" : "+l"(d) : "l"(a), "l"(b));
}

__device__ __forceinline__ float sigm(float a) {
    a = fminf(30.f, fmaxf(-30.f, a));
    float e = __expf(-a);
    return __fdividef(1.f, 1.f + e);
}
__device__ __forceinline__ float tanh_f(float a) {
    a = fminf(15.f, fmaxf(-15.f, a));
    float e = __expf(-2.f * a);
    return __fdividef(1.f - e, 1.f + e);
}

// ---------------------------------------------------------------------------
// GRU kernel: grid = 128 CTAs. CTA handles one sequence (blockIdx>>6) and a
// 64-row batch tile. Per step: Hg[64,192] = H[64,64] @ Whh^T via register-tiled
// SMEM GEMM in packed f32x2, then fused elementwise gate update.
// Thread tile: 4 batch rows (i0..i0+3) x 4 hidden units (h0..h0+3), computing
// all 3 gates for that tile -> no cross-thread gate exchange needed.
// ---------------------------------------------------------------------------
__global__ __launch_bounds__(NTHREADS, 1)
void gru_kernel(const float* __restrict__ x1, const float* __restrict__ x2,
                const float* __restrict__ Wih, const float* __restrict__ Whh,
                const float* __restrict__ bih_g, const float* __restrict__ bhh_g)
{
    extern __shared__ float sm[];
    float* WhhS = sm;                 // [64][192]
    float* HsS  = sm + 12288;         // [64][64]  (HsS[k*64+i] = h[i][k])
    float* xsS  = sm + 12288 + 4096;  // [48][64]  (xsS[(t*3+d)*64+i])

    const int tid = threadIdx.x;
    const int seq = blockIdx.x >> 6;
    const int b0  = (blockIdx.x & 63) * TB;
    const float* xg = (seq == 0) ? x1 : x2;

    const int i0 = (tid & 15) * 4;   // batch-row tile
    const int h0 = (tid >> 4) * 4;   // hidden-unit tile

    // Stage W_hh transposed: WhhS[k][j] = W_hh[j][k]
    for (int idx = tid; idx < H_DIM * G_DIM; idx += NTHREADS) {
        int k = idx / G_DIM, j = idx - k * G_DIM;
        WhhS[idx] = Whh[j * H_DIM + k];
    }
    // h0 state = 0
    for (int idx = tid; idx < H_DIM * TB; idx += NTHREADS) HsS[idx] = 0.f;

    // Per-thread weights/biases in registers
    float wih[3][4][3];
    float bihr[3][4];
    u64   bhh2[3][2];
    #pragma unroll
    for (int g = 0; g < 3; ++g) {
        #pragma unroll
        for (int h = 0; h < 4; ++h) {
            int row = g * 64 + h0 + h;
            bihr[g][h] = bih_g[row];
            #pragma unroll
            for (int d = 0; d < 3; ++d) wih[g][h][d] = Wih[row * 3 + d];
        }
        bhh2[g][0] = pack2(bhh_g[g * 64 + h0 + 0], bhh_g[g * 64 + h0 + 1]);
        bhh2[g][1] = pack2(bhh_g[g * 64 + h0 + 2], bhh_g[g * 64 + h0 + 3]);
    }

    float hprev[4][4];   // [h][i], this thread's tile of the state
    #pragma unroll
    for (int h = 0; h < 4; ++h)
        #pragma unroll
        for (int i = 0; i < 4; ++i) hprev[h][i] = 0.f;

    __syncthreads();

    for (int t0 = 0; t0 < T_LEN; t0 += XC) {
        // Stage x[t0..t0+15] transposed into SMEM (coalesced 16B global loads)
        for (int idx = tid; idx < TB * 12; idx += NTHREADS) {
            int row = idx / 12, q = idx - row * 12;
            const float4 v = *(const float4*)(xg + (size_t)(b0 + row) * (T_LEN * D_IN)
                                                 + t0 * D_IN + q * 4);
            xsS[(q * 4 + 0) * 64 + row] = v.x;
            xsS[(q * 4 + 1) * 64 + row] = v.y;
            xsS[(q * 4 + 2) * 64 + row] = v.z;
            xsS[(q * 4 + 3) * 64 + row] = v.w;
        }
        __syncthreads();

        #pragma unroll 1
        for (int tt = 0; tt < XC; ++tt) {
            // ---- GEMM: acc[g][q][i] packs gates (h0+2q, h0+2q+1) for row i0+i
            u64 acc[3][2][4];
            #pragma unroll
            for (int g = 0; g < 3; ++g)
                #pragma unroll
                for (int q = 0; q < 2; ++q)
                    #pragma unroll
                    for (int i = 0; i < 4; ++i) acc[g][q][i] = bhh2[g][q];

            #pragma unroll 8
            for (int k = 0; k < H_DIM; ++k) {
                const float4 av = *(const float4*)(HsS + k * 64 + i0);   // conflict-free
                u64 ad[4] = { pack2(av.x, av.x), pack2(av.y, av.y),
                              pack2(av.z, av.z), pack2(av.w, av.w) };
                #pragma unroll
                for (int g = 0; g < 3; ++g) {
                    const ulonglong2 wv =
                        *(const ulonglong2*)(WhhS + k * G_DIM + g * 64 + h0); // broadcast
                    #pragma unroll
                    for (int i = 0; i < 4; ++i) {
                        ffma2(acc[g][0][i], ad[i], wv.x);
                        ffma2(acc[g][1][i], ad[i], wv.y);
                    }
                }
            }
            __syncthreads();   // all Hs reads done before rewriting Hs

            // ---- x contribution for my 4 rows
            float xr4[3][4];
            #pragma unroll
            for (int d = 0; d < 3; ++d) {
                const float4 v = *(const float4*)(xsS + (tt * 3 + d) * 64 + i0);
                xr4[d][0] = v.x; xr4[d][1] = v.y; xr4[d][2] = v.z; xr4[d][3] = v.w;
            }

            // ---- Fused gate elementwise
            #pragma unroll
            for (int q = 0; q < 2; ++q) {
                float hr[2][4], hz[2][4], hn[2][4];
                #pragma unroll
                for (int i = 0; i < 4; ++i) {
                    unpack2(acc[0][q][i], hr[0][i], hr[1][i]);
                    unpack2(acc[1][q][i], hz[0][i], hz[1][i]);
                    unpack2(acc[2][q][i], hn[0][i], hn[1][i]);
                }
                #pragma unroll
                for (int s = 0; s < 2; ++s) {
                    const int h = 2 * q + s;
                    #pragma unroll
                    for (int i = 0; i < 4; ++i) {
                        float xr = bihr[0][h] + xr4[0][i]*wih[0][h][0]
                                             + xr4[1][i]*wih[0][h][1]
                                             + xr4[2][i]*wih[0][h][2];
                        float xz = bihr[1][h] + xr4[0][i]*wih[1][h][0]
                                             + xr4[1][i]*wih[1][h][1]
                                             + xr4[2][i]*wih[1][h][2];
                        float xn = bihr[2][h] + xr4[0][i]*wih[2][h][0]
                                             + xr4[1][i]*wih[2][h][1]
                                             + xr4[2][i]*wih[2][h][2];
                        float r = sigm(xr + hr[s][i]);
                        float z = sigm(xz + hz[s][i]);
                        float n = tanh_f(xn + r * hn[s][i]);
                        hprev[h][i] = n + z * (hprev[h][i] - n);
                    }
                }
            }

            // ---- Write new state (conflict-free STS.128)
            #pragma unroll
            for (int h = 0; h < 4; ++h)
                *(float4*)(HsS + (h0 + h) * 64 + i0) =
                    make_float4(hprev[h][0], hprev[h][1], hprev[h][2], hprev[h][3]);
            __syncthreads();
        }
    }

    // Final hidden state -> global scratch
    #pragma unroll
    for (int i = 0; i < 4; ++i) {
        float4 v = make_float4(hprev[0][i], hprev[1][i], hprev[2][i], hprev[3][i]);
        *(float4*)(g_hfinal + ((size_t)seq * BATCH + b0 + i0 + i) * H_DIM + h0) = v;
    }
}

// ---------------------------------------------------------------------------
// MLP head: |h1-h2| -> Linear(64,32)+ReLU -> Linear(32,1)+Sigmoid
// One warp per batch row; hidden unit j = lane (32 hidden units = warp width).
// ---------------------------------------------------------------------------
__global__ __launch_bounds__(128)
void mlp_kernel(const float* __restrict__ W1, const float* __restrict__ b1,
                const float* __restrict__ W2, const float* __restrict__ b2,
                float* __restrict__ out)
{
    __shared__ float sW1[32][65];   // padded: conflict-free sW1[lane][k]
    __shared__ float sb1[32], sW2[32];
    const int tid = threadIdx.x;
    for (int idx = tid; idx < 32 * 64; idx += 128) sW1[idx >> 6][idx & 63] = W1[idx];
    if (tid < 32) { sb1[tid] = b1[tid]; sW2[tid] = W2[tid]; }
    __syncthreads();

    const int lane = tid & 31;
    const int row  = blockIdx.x * 4 + (tid >> 5);
    const float* h1 = g_hfinal + (size_t)row * H_DIM;
    const float* h2 = g_hfinal + (size_t)(BATCH + row) * H_DIM;
    float d0 = fabsf(h1[lane]      - h2[lane]);
    float d1 = fabsf(h1[lane + 32] - h2[lane + 32]);

    float acc = sb1[lane];
    #pragma unroll
    for (int k = 0; k < 32; ++k) {
        float v0 = __shfl_sync(0xffffffffu, d0, k);
        float v1 = __shfl_sync(0xffffffffu, d1, k);
        acc += v0 * sW1[lane][k] + v1 * sW1[lane][k + 32];
    }
    float hid = fmaxf(acc, 0.f);
    float p = hid * sW2[lane];
    #pragma unroll
    for (int o = 16; o; o >>= 1) p += __shfl_xor_sync(0xffffffffu, p, o);
    if (lane == 0) out[row] = sigm(p + b2[0]);
}

// ---------------------------------------------------------------------------
extern "C" void kernel_launch(void* const* d_in, const int* in_sizes, int n_in,
                              void* d_out, int out_size)
{
    const float* x1  = (const float*)d_in[0];
    const float* x2  = (const float*)d_in[1];
    const float* Wih = (const float*)d_in[2];
    const float* Whh = (const float*)d_in[3];
    const float* bih = (const float*)d_in[4];
    const float* bhh = (const float*)d_in[5];
    const float* W1  = (const float*)d_in[6];
    const float* b1  = (const float*)d_in[7];
    const float* W2  = (const float*)d_in[8];
    const float* b2  = (const float*)d_in[9];

    cudaFuncSetAttribute((const void*)gru_kernel,
                         cudaFuncAttributeMaxDynamicSharedMemorySize, SMEM_BYTES);

    gru_kernel<<<128, NTHREADS, SMEM_BYTES>>>(x1, x2, Wih, Whh, bih, bhh);
    mlp_kernel<<<BATCH / 4, 128>>>(W1, b1, W2, b2, (float*)d_out);
}